// round 15
// baseline (speedup 1.0000x reference)
#include <cuda_runtime.h>
#include <cuda_fp16.h>
#include <math.h>
#include <stdint.h>

#define EMBED  512
#define NHEADS 8
#define HDIM   64
#define BATCH  4
#define SEQ    2048
#define MTOT   (BATCH*SEQ)   // 8192

// Scratch (device globals — no runtime allocation)
__device__ __half g_xh[MTOT*EMBED];             // x in fp16
__device__ __half g_wh[4*EMBED*EMBED];          // Wq,Wk,Wv,Wo in fp16
__device__ __half g_q[BATCH*NHEADS*SEQ*HDIM];   // [B,H,S,D] fp16
__device__ __half g_k[BATCH*NHEADS*SEQ*HDIM];   // [B,H,S,D] fp16
__device__ __half g_v[BATCH*NHEADS*SEQ*HDIM];   // [B,H,S,D] fp16
__device__ __half g_o[BATCH*SEQ*EMBED];         // [B,S,E] fp16

__device__ __forceinline__ float gelu_f(float x) {
    return 0.5f * x * (1.0f + erff(x * 0.70710678118654752440f));
}

__device__ __forceinline__ uint32_t packh(float a, float b) {
    __half2 h = __floats2half2_rn(a, b);
    return *(uint32_t*)&h;
}

__device__ __forceinline__ float fexp2(float x) {
    float y;
    asm("ex2.approx.ftz.f32 %0, %1;" : "=f"(y) : "f"(x));
    return y;
}

__device__ __forceinline__ uint32_t sptr(const void* p) {
    return (uint32_t)__cvta_generic_to_shared(p);
}

__device__ __forceinline__ void cpasync16(uint32_t dst, const void* src) {
    asm volatile("cp.async.ca.shared.global [%0], [%1], 16;" :: "r"(dst), "l"(src));
}
__device__ __forceinline__ void cp_commit() {
    asm volatile("cp.async.commit_group;");
}
template<int N>
__device__ __forceinline__ void cp_wait() {
    asm volatile("cp.async.wait_group %0;" :: "n"(N));
}

__device__ __forceinline__ void mma_f16(float c[4], const uint32_t a[4], const uint32_t b[2]) {
    asm volatile(
        "mma.sync.aligned.m16n8k16.row.col.f32.f16.f16.f32 "
        "{%0,%1,%2,%3},{%4,%5,%6,%7},{%8,%9},{%0,%1,%2,%3};"
        : "+f"(c[0]), "+f"(c[1]), "+f"(c[2]), "+f"(c[3])
        : "r"(a[0]), "r"(a[1]), "r"(a[2]), "r"(a[3]), "r"(b[0]), "r"(b[1]));
}

__device__ __forceinline__ void ldsm4(uint32_t r[4], uint32_t saddr) {
    asm volatile("ldmatrix.sync.aligned.m8n8.x4.shared.b16 {%0,%1,%2,%3}, [%4];"
                 : "=r"(r[0]), "=r"(r[1]), "=r"(r[2]), "=r"(r[3]) : "r"(saddr));
}

__device__ __forceinline__ void ldsm4t(uint32_t r[4], uint32_t saddr) {
    asm volatile("ldmatrix.sync.aligned.m8n8.x4.trans.shared.b16 {%0,%1,%2,%3}, [%4];"
                 : "=r"(r[0]), "=r"(r[1]), "=r"(r[2]), "=r"(r[3]) : "r"(saddr));
}

// ---------------------------------------------------------------------------
// Convert x and all four weight matrices to fp16 (one memory-bound pass).
// ---------------------------------------------------------------------------
__global__ __launch_bounds__(256)
void convert_f2h(const float* __restrict__ x,
                 const float* __restrict__ Wq, const float* __restrict__ Wk,
                 const float* __restrict__ Wv, const float* __restrict__ Wo) {
    const int XC = MTOT * EMBED / 4;
    const int WC = EMBED * EMBED / 4;
    int i = blockIdx.x * 256 + threadIdx.x;
    float4 v;
    uint2* dst;
    if (i < XC) {
        v = ((const float4*)x)[i];
        dst = (uint2*)g_xh + i;
    } else {
        int j = i - XC;
        int w = j / WC, off = j - w * WC;
        const float* Ws = (w == 0) ? Wq : (w == 1) ? Wk : (w == 2) ? Wv : Wo;
        v = ((const float4*)Ws)[off];
        dst = (uint2*)g_wh + j;
    }
    uint2 p;
    p.x = packh(v.x, v.y);
    p.y = packh(v.z, v.w);
    *dst = p;
}

// ---------------------------------------------------------------------------
// GEMM core: C = gelu(A @ W^T + bias). A,W fp16. Block tile 128x64, 8 warps
// (4m x 2n), warp tile 32x32, BK=64, 2-stage cp.async, 1 sync/iter.
// Smem row = 64 halves + 4 pad = 36 words.
// Dynamic smem: 2 stages x (A 18432B + W 9216B) = 55296B -> 3-4 CTAs/SM.
// ---------------------------------------------------------------------------
#define G_ABYTES 18432u          // 128 rows * 36 words * 4B
#define G_WBYTES 9216u           // 64 rows * 36 words * 4B
#define G_WOFF   G_ABYTES
#define G_STB    27648u          // stage stride

template<bool OHALF>
__device__ __forceinline__ void gemm_core(const __half* __restrict__ A,
                                          const __half* __restrict__ W,
                                          const float* __restrict__ bias, void* Cout) {
    extern __shared__ __align__(16) uint32_t dynsmem[];
    const uint32_t base = sptr(dynsmem);

    const int t    = threadIdx.x;
    const int lane = t & 31;
    const int warp = t >> 5;          // 0..7
    const int wm   = warp >> 1;       // 0..3
    const int wn   = warp & 1;        // 0..1
    const int m0   = blockIdx.y * 128;
    const int n0   = blockIdx.x * 64;
    const int r    = lane >> 2;
    const int cc   = lane & 3;

    const uint32_t a_loff = (((lane & 15) * 36) + ((lane >> 4) * 4)) * 4;
    const uint32_t b_loff = ((((lane & 7) + ((lane >> 4) * 8)) * 36) + (((lane >> 3) & 1) * 4)) * 4;
    const uint32_t as_w = base + (uint32_t)(wm * 32 * 36) * 4 + a_loff;
    const uint32_t ws_w = base + G_WOFF + (uint32_t)(wn * 32 * 36) * 4 + b_loff;

    // A staging: 2 threads/row, 64B each (4 x cp.async16)
    const int arw  = t >> 1;          // 0..127
    const int awo  = (t & 1) * 16;    // word offset {0,16}
    const __half* arow = A + (size_t)(m0 + arw) * EMBED + awo * 2;
    const uint32_t adst = base + (uint32_t)(arw * 36 + awo) * 4;
    // W staging: 4 threads/row, 32B each (2 x cp.async16)
    const int wrw  = t >> 2;          // 0..63
    const int wwo  = (t & 3) * 8;     // word offset {0,8,16,24}
    const __half* wrow = W + (size_t)(n0 + wrw) * EMBED + wwo * 2;
    const uint32_t wdst = base + G_WOFF + (uint32_t)(wrw * 36 + wwo) * 4;

    float acc[2][4][4];
    #pragma unroll
    for (int mi = 0; mi < 2; ++mi)
        #pragma unroll
        for (int nf = 0; nf < 4; ++nf)
            #pragma unroll
            for (int j = 0; j < 4; ++j) acc[mi][nf][j] = 0.0f;

    // prologue: issue chunk 0
    #pragma unroll
    for (int c = 0; c < 4; ++c)
        cpasync16(adst + c * 16, arow + c * 8);
    #pragma unroll
    for (int c = 0; c < 2; ++c)
        cpasync16(wdst + c * 16, wrow + c * 8);
    cp_commit();

    #pragma unroll 1
    for (int i = 0; i < 8; ++i) {
        cp_wait<0>();
        __syncthreads();

        // issue chunk i+1 into the other buffer (consumed at i-1; drained)
        if (i + 1 < 8) {
            const uint32_t so = (uint32_t)((i + 1) & 1) * G_STB;
            const int k0 = (i + 1) * 64;
            #pragma unroll
            for (int c = 0; c < 4; ++c)
                cpasync16(adst + so + c * 16, arow + k0 + c * 8);
            #pragma unroll
            for (int c = 0; c < 2; ++c)
                cpasync16(wdst + so + c * 16, wrow + k0 + c * 8);
            cp_commit();
        }

        const uint32_t sb = (uint32_t)(i & 1) * G_STB;
        const uint32_t aw = as_w + sb;
        const uint32_t ww = ws_w + sb;
        #pragma unroll
        for (int ks = 0; ks < 4; ++ks) {
            uint32_t a[2][4], b[2][4];
            #pragma unroll
            for (int mi = 0; mi < 2; ++mi)
                ldsm4(a[mi], aw + (uint32_t)(mi * 16 * 36) * 4 + ks * 32);
            #pragma unroll
            for (int np = 0; np < 2; ++np)
                ldsm4(b[np], ww + (uint32_t)(np * 16 * 36) * 4 + ks * 32);
            #pragma unroll
            for (int mi = 0; mi < 2; ++mi)
                #pragma unroll
                for (int np = 0; np < 2; ++np) {
                    mma_f16(acc[mi][2 * np],     a[mi], &b[np][0]);
                    mma_f16(acc[mi][2 * np + 1], a[mi], &b[np][2]);
                }
        }
    }

    // Epilogue: bias + gelu, store
    #pragma unroll
    for (int mi = 0; mi < 2; ++mi) {
        #pragma unroll
        for (int nf = 0; nf < 4; ++nf) {
            int row = m0 + wm * 32 + mi * 16 + r;
            int col = n0 + wn * 32 + nf * 8 + 2 * cc;
            float b0 = bias[col], b1 = bias[col + 1];
            float e00 = gelu_f(acc[mi][nf][0] + b0);
            float e01 = gelu_f(acc[mi][nf][1] + b1);
            float e10 = gelu_f(acc[mi][nf][2] + b0);
            float e11 = gelu_f(acc[mi][nf][3] + b1);
            if (!OHALF) {
                float* C = (float*)Cout;
                float2 v0 = {e00, e01}, v1 = {e10, e11};
                *(float2*)(C + (size_t)row * EMBED + col)       = v0;
                *(float2*)(C + (size_t)(row + 8) * EMBED + col) = v1;
            } else {
                __half* C = (__half*)Cout;
                int bz = row >> 11, s = row & (SEQ - 1);
                int h = col >> 6, d = col & 63;
                *(uint32_t*)&C[(((size_t)(bz * NHEADS + h) * SEQ + s) * HDIM + d)]       = packh(e00, e01);
                *(uint32_t*)&C[(((size_t)(bz * NHEADS + h) * SEQ + (s + 8)) * HDIM + d)] = packh(e10, e11);
            }
        }
    }
}

__global__ __launch_bounds__(256)
void qkv_proj(const float* __restrict__ bq, const float* __restrict__ bk,
              const float* __restrict__ bv) {
    const int z = blockIdx.z;
    const float* bias = (z == 0) ? bq : (z == 1) ? bk : bv;
    __half* C         = (z == 0) ? g_q : (z == 1) ? g_k : g_v;
    gemm_core<true>(g_xh, g_wh + (size_t)z * EMBED * EMBED, bias, C);
}

__global__ __launch_bounds__(256)
void out_proj(const float* __restrict__ bo, float* __restrict__ out) {
    gemm_core<false>(g_o, g_wh + (size_t)3 * EMBED * EMBED, bo, out);
}

// ---------------------------------------------------------------------------
// Flash attention (unchanged from R14). Q,K,V: [B*H,S,64] fp16, O: [B,S,E] fp16.
// 128 threads = 4 warps; warp owns 32 q rows. KV tile = 64.
// 2-stage cp.async, ONE sync per tile; P entirely in registers.
// Dynamic smem: 2 stages x (K 9216B + V 9216B) = 36864B.
// ---------------------------------------------------------------------------
#define F_STB   18432u
#define F_VOFF  9216u

__global__ __launch_bounds__(128)
void flash_mma(const __half* __restrict__ Q, const __half* __restrict__ K,
               const __half* __restrict__ V, __half* __restrict__ O) {
    extern __shared__ __align__(16) uint32_t dynsmem[];
    const uint32_t base = sptr(dynsmem);

    const int t    = threadIdx.x;
    const int lane = t & 31;
    const int w    = t >> 5;
    const int bh   = blockIdx.y;
    const int qt   = blockIdx.x;
    const int r    = lane >> 2;
    const int cc   = lane & 3;

    const uint32_t b_loff = ((((lane & 7) + ((lane >> 4) * 8)) * 36) + (((lane >> 3) & 1) * 4)) * 4;
    const uint32_t t_loff = (((lane & 15) * 36) + ((lane >> 4) * 4)) * 4;
    const uint32_t skb = base + b_loff;
    const uint32_t svb = base + F_VOFF + t_loff;

    const int lrow = t >> 1;
    const int lw16 = (t & 1) * 16;
    const __half* kbase = K + ((size_t)bh * SEQ + lrow) * HDIM + lw16 * 2;
    const __half* vbase = V + ((size_t)bh * SEQ + lrow) * HDIM + lw16 * 2;
    const uint32_t kdst = base + (uint32_t)(lrow * 36 + lw16) * 4;
    const uint32_t vdst = kdst + F_VOFF;

    const float SC = 0.18033688011112042f;
    const __half2 sc2 = __floats2half2_rn(SC, SC);
    uint32_t qf[2][4][4];
    const __half* qb = Q + ((size_t)bh * SEQ + qt * 128 + w * 32) * HDIM;
    #pragma unroll
    for (int mi = 0; mi < 2; ++mi) {
        #pragma unroll
        for (int kf = 0; kf < 4; ++kf) {
            int row0 = mi * 16 + r;
            uint32_t u0 = *(const uint32_t*)&qb[(size_t)row0 * HDIM + kf * 16 + cc * 2];
            uint32_t u1 = *(const uint32_t*)&qb[(size_t)(row0 + 8) * HDIM + kf * 16 + cc * 2];
            uint32_t u2 = *(const uint32_t*)&qb[(size_t)row0 * HDIM + kf * 16 + 8 + cc * 2];
            uint32_t u3 = *(const uint32_t*)&qb[(size_t)(row0 + 8) * HDIM + kf * 16 + 8 + cc * 2];
            __half2 h0 = __hmul2(*(__half2*)&u0, sc2);
            __half2 h1 = __hmul2(*(__half2*)&u1, sc2);
            __half2 h2 = __hmul2(*(__half2*)&u2, sc2);
            __half2 h3 = __hmul2(*(__half2*)&u3, sc2);
            qf[mi][kf][0] = *(uint32_t*)&h0;
            qf[mi][kf][1] = *(uint32_t*)&h1;
            qf[mi][kf][2] = *(uint32_t*)&h2;
            qf[mi][kf][3] = *(uint32_t*)&h3;
        }
    }

    float o[2][8][4];
    #pragma unroll
    for (int mi = 0; mi < 2; ++mi)
        #pragma unroll
        for (int nf = 0; nf < 8; ++nf)
            #pragma unroll
            for (int j = 0; j < 4; ++j) o[mi][nf][j] = 0.0f;
    float m_i[2][2] = {{-1e30f, -1e30f}, {-1e30f, -1e30f}};
    float l_i[2][2] = {{0.0f, 0.0f}, {0.0f, 0.0f}};

    // prologue: issue tile 0
    cpasync16(kdst,      kbase);
    cpasync16(kdst + 16, kbase + 8);
    cpasync16(kdst + 32, kbase + 16);
    cpasync16(kdst + 48, kbase + 24);
    cpasync16(vdst,      vbase);
    cpasync16(vdst + 16, vbase + 8);
    cpasync16(vdst + 32, vbase + 16);
    cpasync16(vdst + 48, vbase + 24);
    cp_commit();

    const int NT = SEQ / 64;
    #pragma unroll 1
    for (int kt = 0; kt < NT; ++kt) {
        cp_wait<0>();
        __syncthreads();

        if (kt + 1 < NT) {
            const uint32_t boff = ((kt + 1) & 1) * F_STB;
            const size_t goff = (size_t)(kt + 1) * 64 * HDIM;
            cpasync16(kdst + boff,      kbase + goff);
            cpasync16(kdst + boff + 16, kbase + goff + 8);
            cpasync16(kdst + boff + 32, kbase + goff + 16);
            cpasync16(kdst + boff + 48, kbase + goff + 24);
            cpasync16(vdst + boff,      vbase + goff);
            cpasync16(vdst + boff + 16, vbase + goff + 8);
            cpasync16(vdst + boff + 32, vbase + goff + 16);
            cpasync16(vdst + boff + 48, vbase + goff + 24);
            cp_commit();
        }

        const uint32_t sb = (uint32_t)(kt & 1) * F_STB;

        // S = Q @ K^T
        float s[2][8][4];
        #pragma unroll
        for (int mi = 0; mi < 2; ++mi)
            #pragma unroll
            for (int nf = 0; nf < 8; ++nf)
                #pragma unroll
                for (int j = 0; j < 4; ++j) s[mi][nf][j] = 0.0f;

        const uint32_t skw = skb + sb;
        #pragma unroll
        for (int kf = 0; kf < 4; ++kf) {
            #pragma unroll
            for (int nfp = 0; nfp < 4; ++nfp) {
                uint32_t bb[4];
                ldsm4(bb, skw + (uint32_t)(nfp * 16 * 36) * 4 + kf * 32);
                #pragma unroll
                for (int mi = 0; mi < 2; ++mi) {
                    mma_f16(s[mi][2 * nfp],     qf[mi][kf], &bb[0]);
                    mma_f16(s[mi][2 * nfp + 1], qf[mi][kf], &bb[2]);
                }
            }
        }

        // Online softmax (log2 domain) + pack P into registers
        uint32_t pf[2][4][4];
        #pragma unroll
        for (int mi = 0; mi < 2; ++mi) {
            float mx0 = -1e30f, mx1 = -1e30f;
            #pragma unroll
            for (int nf = 0; nf < 8; ++nf) {
                mx0 = fmaxf(mx0, fmaxf(s[mi][nf][0], s[mi][nf][1]));
                mx1 = fmaxf(mx1, fmaxf(s[mi][nf][2], s[mi][nf][3]));
            }
            mx0 = fmaxf(mx0, __shfl_xor_sync(0xffffffffu, mx0, 1));
            mx0 = fmaxf(mx0, __shfl_xor_sync(0xffffffffu, mx0, 2));
            mx1 = fmaxf(mx1, __shfl_xor_sync(0xffffffffu, mx1, 1));
            mx1 = fmaxf(mx1, __shfl_xor_sync(0xffffffffu, mx1, 2));

            float mn0 = fmaxf(m_i[mi][0], mx0);
            float mn1 = fmaxf(m_i[mi][1], mx1);
            float corr0 = fexp2(m_i[mi][0] - mn0);
            float corr1 = fexp2(m_i[mi][1] - mn1);

            float rs0 = 0.0f, rs1 = 0.0f;
            #pragma unroll
            for (int nf = 0; nf < 8; ++nf) {
                s[mi][nf][0] = fexp2(s[mi][nf][0] - mn0);
                s[mi][nf][1] = fexp2(s[mi][nf][1] - mn0);
                s[mi][nf][2] = fexp2(s[mi][nf][2] - mn1);
                s[mi][nf][3] = fexp2(s[mi][nf][3] - mn1);
                rs0 += s[mi][nf][0] + s[mi][nf][1];
                rs1 += s[mi][nf][2] + s[mi][nf][3];
            }
            rs0 += __shfl_xor_sync(0xffffffffu, rs0, 1);
            rs0 += __shfl_xor_sync(0xffffffffu, rs0, 2);
            rs1 += __shfl_xor_sync(0xffffffffu, rs1, 1);
            rs1 += __shfl_xor_sync(0xffffffffu, rs1, 2);

            l_i[mi][0] = l_i[mi][0] * corr0 + rs0;
            l_i[mi][1] = l_i[mi][1] * corr1 + rs1;
            m_i[mi][0] = mn0;
            m_i[mi][1] = mn1;

            #pragma unroll
            for (int nf = 0; nf < 8; ++nf) {
                o[mi][nf][0] *= corr0; o[mi][nf][1] *= corr0;
                o[mi][nf][2] *= corr1; o[mi][nf][3] *= corr1;
            }

            #pragma unroll
            for (int kf = 0; kf < 4; ++kf) {
                pf[mi][kf][0] = packh(s[mi][2 * kf][0],     s[mi][2 * kf][1]);
                pf[mi][kf][1] = packh(s[mi][2 * kf][2],     s[mi][2 * kf][3]);
                pf[mi][kf][2] = packh(s[mi][2 * kf + 1][0], s[mi][2 * kf + 1][1]);
                pf[mi][kf][3] = packh(s[mi][2 * kf + 1][2], s[mi][2 * kf + 1][3]);
            }
        }

        // O += P @ V  (row-major V tile, B-frags via ldmatrix.trans)
        const uint32_t svw = svb + sb;
        #pragma unroll
        for (int kf = 0; kf < 4; ++kf) {
            #pragma unroll
            for (int nfp = 0; nfp < 4; ++nfp) {
                uint32_t bb[4];
                ldsm4t(bb, svw + (uint32_t)(kf * 16 * 36) * 4 + nfp * 32);
                #pragma unroll
                for (int mi = 0; mi < 2; ++mi) {
                    mma_f16(o[mi][2 * nfp],     pf[mi][kf], &bb[0]);
                    mma_f16(o[mi][2 * nfp + 1], pf[mi][kf], &bb[2]);
                }
            }
        }
    }

    int bz = bh >> 3, h = bh & 7;
    #pragma unroll
    for (int mi = 0; mi < 2; ++mi) {
        float inv0 = 1.0f / l_i[mi][0];
        float inv1 = 1.0f / l_i[mi][1];
        int row0 = qt * 128 + w * 32 + mi * 16 + r;
        __half* op0 = O + ((size_t)bz * SEQ + row0) * EMBED + h * HDIM;
        __half* op1 = O + ((size_t)bz * SEQ + row0 + 8) * EMBED + h * HDIM;
        #pragma unroll
        for (int nf = 0; nf < 8; ++nf) {
            *(uint32_t*)(op0 + nf * 8 + 2 * cc) = packh(o[mi][nf][0] * inv0, o[mi][nf][1] * inv0);
            *(uint32_t*)(op1 + nf * 8 + 2 * cc) = packh(o[mi][nf][2] * inv1, o[mi][nf][3] * inv1);
        }
    }
}

extern "C" void kernel_launch(void* const* d_in, const int* in_sizes, int n_in,
                              void* d_out, int out_size) {
    const float* x  = (const float*)d_in[0];
    const float* Wq = (const float*)d_in[1];
    const float* bq = (const float*)d_in[2];
    const float* Wk = (const float*)d_in[3];
    const float* bk = (const float*)d_in[4];
    const float* Wv = (const float*)d_in[5];
    const float* bv = (const float*)d_in[6];
    const float* Wo = (const float*)d_in[7];
    const float* bo = (const float*)d_in[8];
    float* out = (float*)d_out;

    __half *gq, *gk, *gv, *go;
    cudaGetSymbolAddress((void**)&gq, g_q);
    cudaGetSymbolAddress((void**)&gk, g_k);
    cudaGetSymbolAddress((void**)&gv, g_v);
    cudaGetSymbolAddress((void**)&go, g_o);

    const int GEMM_SMEM  = 2 * (18432 + 9216);    // 55296
    const int FLASH_SMEM = 2 * 2 * 64 * 36 * 4;   // 36864
    cudaFuncSetAttribute(qkv_proj,  cudaFuncAttributeMaxDynamicSharedMemorySize, GEMM_SMEM);
    cudaFuncSetAttribute(out_proj,  cudaFuncAttributeMaxDynamicSharedMemorySize, GEMM_SMEM);
    cudaFuncSetAttribute(flash_mma, cudaFuncAttributeMaxDynamicSharedMemorySize, FLASH_SMEM);

    const int XC = MTOT * EMBED / 4;
    const int WC = EMBED * EMBED / 4;
    convert_f2h<<<(XC + 4 * WC) / 256, 256>>>(x, Wq, Wk, Wv, Wo);

    dim3 gridP(EMBED / 64, MTOT / 128, 3);   // (8, 64, 3)
    qkv_proj<<<gridP, 256, GEMM_SMEM>>>(bq, bk, bv);

    dim3 gridA(SEQ / 128, BATCH * NHEADS);   // (16, 32)
    flash_mma<<<gridA, 128, FLASH_SMEM>>>(gq, gk, gv, go);

    dim3 gridO(EMBED / 64, MTOT / 128);      // (8, 64)
    out_proj<<<gridO, 256, GEMM_SMEM>>>(bo, out);
}

// round 16
// speedup vs baseline: 1.0369x; 1.0369x over previous
#include <cuda_runtime.h>
#include <cuda_fp16.h>
#include <math.h>
#include <stdint.h>

#define EMBED  512
#define NHEADS 8
#define HDIM   64
#define BATCH  4
#define SEQ    2048
#define MTOT   (BATCH*SEQ)   // 8192

// Scratch (device globals — no runtime allocation)
__device__ __half g_xh[MTOT*EMBED];             // x in fp16
__device__ __half g_wh[4*EMBED*EMBED];          // Wq,Wk,Wv,Wo in fp16
__device__ __half g_q[BATCH*NHEADS*SEQ*HDIM];   // [B,H,S,D] fp16
__device__ __half g_k[BATCH*NHEADS*SEQ*HDIM];   // [B,H,S,D] fp16
__device__ __half g_v[BATCH*NHEADS*SEQ*HDIM];   // [B,H,S,D] fp16
__device__ __half g_o[BATCH*SEQ*EMBED];         // [B,S,E] fp16

__device__ __forceinline__ float gelu_f(float x) {
    return 0.5f * x * (1.0f + erff(x * 0.70710678118654752440f));
}

__device__ __forceinline__ uint32_t packh(float a, float b) {
    __half2 h = __floats2half2_rn(a, b);
    return *(uint32_t*)&h;
}

__device__ __forceinline__ float fexp2(float x) {
    float y;
    asm("ex2.approx.ftz.f32 %0, %1;" : "=f"(y) : "f"(x));
    return y;
}

__device__ __forceinline__ uint32_t sptr(const void* p) {
    return (uint32_t)__cvta_generic_to_shared(p);
}

__device__ __forceinline__ void cpasync16(uint32_t dst, const void* src) {
    asm volatile("cp.async.ca.shared.global [%0], [%1], 16;" :: "r"(dst), "l"(src));
}
__device__ __forceinline__ void cp_commit() {
    asm volatile("cp.async.commit_group;");
}
template<int N>
__device__ __forceinline__ void cp_wait() {
    asm volatile("cp.async.wait_group %0;" :: "n"(N));
}

__device__ __forceinline__ void mma_f16(float c[4], const uint32_t a[4], const uint32_t b[2]) {
    asm volatile(
        "mma.sync.aligned.m16n8k16.row.col.f32.f16.f16.f32 "
        "{%0,%1,%2,%3},{%4,%5,%6,%7},{%8,%9},{%0,%1,%2,%3};"
        : "+f"(c[0]), "+f"(c[1]), "+f"(c[2]), "+f"(c[3])
        : "r"(a[0]), "r"(a[1]), "r"(a[2]), "r"(a[3]), "r"(b[0]), "r"(b[1]));
}

__device__ __forceinline__ void ldsm4(uint32_t r[4], uint32_t saddr) {
    asm volatile("ldmatrix.sync.aligned.m8n8.x4.shared.b16 {%0,%1,%2,%3}, [%4];"
                 : "=r"(r[0]), "=r"(r[1]), "=r"(r[2]), "=r"(r[3]) : "r"(saddr));
}

__device__ __forceinline__ void ldsm4t(uint32_t r[4], uint32_t saddr) {
    asm volatile("ldmatrix.sync.aligned.m8n8.x4.trans.shared.b16 {%0,%1,%2,%3}, [%4];"
                 : "=r"(r[0]), "=r"(r[1]), "=r"(r[2]), "=r"(r[3]) : "r"(saddr));
}

// ---------------------------------------------------------------------------
// Convert x and all four weight matrices to fp16 (one memory-bound pass).
// ---------------------------------------------------------------------------
__global__ __launch_bounds__(256)
void convert_f2h(const float* __restrict__ x,
                 const float* __restrict__ Wq, const float* __restrict__ Wk,
                 const float* __restrict__ Wv, const float* __restrict__ Wo) {
    const int XC = MTOT * EMBED / 4;
    const int WC = EMBED * EMBED / 4;
    int i = blockIdx.x * 256 + threadIdx.x;
    float4 v;
    uint2* dst;
    if (i < XC) {
        v = ((const float4*)x)[i];
        dst = (uint2*)g_xh + i;
    } else {
        int j = i - XC;
        int w = j / WC, off = j - w * WC;
        const float* Ws = (w == 0) ? Wq : (w == 1) ? Wk : (w == 2) ? Wv : Wo;
        v = ((const float4*)Ws)[off];
        dst = (uint2*)g_wh + j;
    }
    uint2 p;
    p.x = packh(v.x, v.y);
    p.y = packh(v.z, v.w);
    *dst = p;
}

// ---------------------------------------------------------------------------
// GEMM core (R10 config + fragment pipelining): C = gelu(A @ W^T + bias).
// Block tile 128x128, 8 warps (2m x 4n), warp tile 64x32, BK=64, 2-stage
// cp.async, 1 sync/iter. Register ping-pong on ldmatrix fragments.
// Dynamic smem: 2 stages x (A 18432B + W 18432B) = 73728B.
// ---------------------------------------------------------------------------
#define G_ABYTES 18432u
#define G_WOFF   G_ABYTES
#define G_STB    36864u

template<bool OHALF>
__device__ __forceinline__ void gemm_core(const __half* __restrict__ A,
                                          const __half* __restrict__ W,
                                          const float* __restrict__ bias, void* Cout) {
    extern __shared__ __align__(16) uint32_t dynsmem[];
    const uint32_t base = sptr(dynsmem);

    const int t    = threadIdx.x;
    const int lane = t & 31;
    const int warp = t >> 5;
    const int wm   = warp >> 2;       // 0..1
    const int wn   = warp & 3;        // 0..3
    const int m0   = blockIdx.y * 128;
    const int n0   = blockIdx.x * 128;
    const int r    = lane >> 2;
    const int cc   = lane & 3;

    const uint32_t a_loff = (((lane & 15) * 36) + ((lane >> 4) * 4)) * 4;
    const uint32_t b_loff = ((((lane & 7) + ((lane >> 4) * 8)) * 36) + (((lane >> 3) & 1) * 4)) * 4;
    const uint32_t as_w = base + (uint32_t)(wm * 64 * 36) * 4 + a_loff;
    const uint32_t ws_w = base + G_WOFF + (uint32_t)(wn * 32 * 36) * 4 + b_loff;

    const int lrow = t >> 1;
    const int lw16 = (t & 1) * 16;
    const __half* arow = A + (size_t)(m0 + lrow) * EMBED + lw16 * 2;
    const __half* wrow = W + (size_t)(n0 + lrow) * EMBED + lw16 * 2;
    const uint32_t adst = base + (uint32_t)(lrow * 36 + lw16) * 4;
    const uint32_t wdst = adst + G_WOFF;

    float acc[4][4][4];
    #pragma unroll
    for (int mi = 0; mi < 4; ++mi)
        #pragma unroll
        for (int ni = 0; ni < 4; ++ni)
            #pragma unroll
            for (int j = 0; j < 4; ++j) acc[mi][ni][j] = 0.0f;

    // prologue: issue chunk 0
    #pragma unroll
    for (int c = 0; c < 4; ++c) {
        cpasync16(adst + c * 16, arow + c * 8);
        cpasync16(wdst + c * 16, wrow + c * 8);
    }
    cp_commit();

    #pragma unroll 1
    for (int i = 0; i < 8; ++i) {
        cp_wait<0>();
        __syncthreads();

        if (i + 1 < 8) {
            const uint32_t so = (uint32_t)((i + 1) & 1) * G_STB;
            const int k0 = (i + 1) * 64;
            #pragma unroll
            for (int c = 0; c < 4; ++c) {
                cpasync16(adst + so + c * 16, arow + k0 + c * 8);
                cpasync16(wdst + so + c * 16, wrow + k0 + c * 8);
            }
            cp_commit();
        }

        const uint32_t sb = (uint32_t)(i & 1) * G_STB;
        const uint32_t aw = as_w + sb;
        const uint32_t ww = ws_w + sb;

        // fragment ping-pong: load ks+1 while mma-ing ks
        uint32_t a[2][4][4], b[2][2][4];
        #pragma unroll
        for (int mi = 0; mi < 4; ++mi)
            ldsm4(a[0][mi], aw + (uint32_t)(mi * 16 * 36) * 4);
        #pragma unroll
        for (int np = 0; np < 2; ++np)
            ldsm4(b[0][np], ww + (uint32_t)(np * 16 * 36) * 4);

        #pragma unroll
        for (int ks = 0; ks < 4; ++ks) {
            const int cur = ks & 1, nxt = cur ^ 1;
            if (ks < 3) {
                #pragma unroll
                for (int mi = 0; mi < 4; ++mi)
                    ldsm4(a[nxt][mi], aw + (uint32_t)(mi * 16 * 36) * 4 + (ks + 1) * 32);
                #pragma unroll
                for (int np = 0; np < 2; ++np)
                    ldsm4(b[nxt][np], ww + (uint32_t)(np * 16 * 36) * 4 + (ks + 1) * 32);
            }
            #pragma unroll
            for (int mi = 0; mi < 4; ++mi)
                #pragma unroll
                for (int np = 0; np < 2; ++np) {
                    mma_f16(acc[mi][2 * np],     a[cur][mi], &b[cur][np][0]);
                    mma_f16(acc[mi][2 * np + 1], a[cur][mi], &b[cur][np][2]);
                }
        }
    }

    // Epilogue: bias + gelu, store
    #pragma unroll
    for (int mi = 0; mi < 4; ++mi) {
        #pragma unroll
        for (int ni = 0; ni < 4; ++ni) {
            int row = m0 + wm * 64 + mi * 16 + r;
            int col = n0 + wn * 32 + ni * 8 + 2 * cc;
            float b0 = bias[col], b1 = bias[col + 1];
            float e00 = gelu_f(acc[mi][ni][0] + b0);
            float e01 = gelu_f(acc[mi][ni][1] + b1);
            float e10 = gelu_f(acc[mi][ni][2] + b0);
            float e11 = gelu_f(acc[mi][ni][3] + b1);
            if (!OHALF) {
                float* C = (float*)Cout;
                float2 v0 = {e00, e01}, v1 = {e10, e11};
                *(float2*)(C + (size_t)row * EMBED + col)       = v0;
                *(float2*)(C + (size_t)(row + 8) * EMBED + col) = v1;
            } else {
                __half* C = (__half*)Cout;
                int bz = row >> 11, s = row & (SEQ - 1);
                int h = col >> 6, d = col & 63;
                *(uint32_t*)&C[(((size_t)(bz * NHEADS + h) * SEQ + s) * HDIM + d)]       = packh(e00, e01);
                *(uint32_t*)&C[(((size_t)(bz * NHEADS + h) * SEQ + (s + 8)) * HDIM + d)] = packh(e10, e11);
            }
        }
    }
}

__global__ __launch_bounds__(256)
void qkv_proj(const float* __restrict__ bq, const float* __restrict__ bk,
              const float* __restrict__ bv) {
    const int z = blockIdx.z;
    const float* bias = (z == 0) ? bq : (z == 1) ? bk : bv;
    __half* C         = (z == 0) ? g_q : (z == 1) ? g_k : g_v;
    gemm_core<true>(g_xh, g_wh + (size_t)z * EMBED * EMBED, bias, C);
}

__global__ __launch_bounds__(256)
void out_proj(const float* __restrict__ bo, float* __restrict__ out) {
    gemm_core<false>(g_o, g_wh + (size_t)3 * EMBED * EMBED, bo, out);
}

// ---------------------------------------------------------------------------
// Flash attention (R14 config + fragment pipelining). Q,K,V: [B*H,S,64] fp16,
// O: [B,S,E] fp16. 128 threads = 4 warps; warp owns 32 q rows. KV tile = 64.
// 2-stage cp.async, ONE sync per tile; P entirely in registers.
// Dynamic smem: 2 stages x (K 9216B + V 9216B) = 36864B.
// ---------------------------------------------------------------------------
#define F_STB   18432u
#define F_VOFF  9216u

__global__ __launch_bounds__(128)
void flash_mma(const __half* __restrict__ Q, const __half* __restrict__ K,
               const __half* __restrict__ V, __half* __restrict__ O) {
    extern __shared__ __align__(16) uint32_t dynsmem[];
    const uint32_t base = sptr(dynsmem);

    const int t    = threadIdx.x;
    const int lane = t & 31;
    const int w    = t >> 5;
    const int bh   = blockIdx.y;
    const int qt   = blockIdx.x;
    const int r    = lane >> 2;
    const int cc   = lane & 3;

    const uint32_t b_loff = ((((lane & 7) + ((lane >> 4) * 8)) * 36) + (((lane >> 3) & 1) * 4)) * 4;
    const uint32_t t_loff = (((lane & 15) * 36) + ((lane >> 4) * 4)) * 4;
    const uint32_t skb = base + b_loff;
    const uint32_t svb = base + F_VOFF + t_loff;

    const int lrow = t >> 1;
    const int lw16 = (t & 1) * 16;
    const __half* kbase = K + ((size_t)bh * SEQ + lrow) * HDIM + lw16 * 2;
    const __half* vbase = V + ((size_t)bh * SEQ + lrow) * HDIM + lw16 * 2;
    const uint32_t kdst = base + (uint32_t)(lrow * 36 + lw16) * 4;
    const uint32_t vdst = kdst + F_VOFF;

    const float SC = 0.18033688011112042f;
    const __half2 sc2 = __floats2half2_rn(SC, SC);
    uint32_t qf[2][4][4];
    const __half* qb = Q + ((size_t)bh * SEQ + qt * 128 + w * 32) * HDIM;
    #pragma unroll
    for (int mi = 0; mi < 2; ++mi) {
        #pragma unroll
        for (int kf = 0; kf < 4; ++kf) {
            int row0 = mi * 16 + r;
            uint32_t u0 = *(const uint32_t*)&qb[(size_t)row0 * HDIM + kf * 16 + cc * 2];
            uint32_t u1 = *(const uint32_t*)&qb[(size_t)(row0 + 8) * HDIM + kf * 16 + cc * 2];
            uint32_t u2 = *(const uint32_t*)&qb[(size_t)row0 * HDIM + kf * 16 + 8 + cc * 2];
            uint32_t u3 = *(const uint32_t*)&qb[(size_t)(row0 + 8) * HDIM + kf * 16 + 8 + cc * 2];
            __half2 h0 = __hmul2(*(__half2*)&u0, sc2);
            __half2 h1 = __hmul2(*(__half2*)&u1, sc2);
            __half2 h2 = __hmul2(*(__half2*)&u2, sc2);
            __half2 h3 = __hmul2(*(__half2*)&u3, sc2);
            qf[mi][kf][0] = *(uint32_t*)&h0;
            qf[mi][kf][1] = *(uint32_t*)&h1;
            qf[mi][kf][2] = *(uint32_t*)&h2;
            qf[mi][kf][3] = *(uint32_t*)&h3;
        }
    }

    float o[2][8][4];
    #pragma unroll
    for (int mi = 0; mi < 2; ++mi)
        #pragma unroll
        for (int nf = 0; nf < 8; ++nf)
            #pragma unroll
            for (int j = 0; j < 4; ++j) o[mi][nf][j] = 0.0f;
    float m_i[2][2] = {{-1e30f, -1e30f}, {-1e30f, -1e30f}};
    float l_i[2][2] = {{0.0f, 0.0f}, {0.0f, 0.0f}};

    // prologue: issue tile 0
    cpasync16(kdst,      kbase);
    cpasync16(kdst + 16, kbase + 8);
    cpasync16(kdst + 32, kbase + 16);
    cpasync16(kdst + 48, kbase + 24);
    cpasync16(vdst,      vbase);
    cpasync16(vdst + 16, vbase + 8);
    cpasync16(vdst + 32, vbase + 16);
    cpasync16(vdst + 48, vbase + 24);
    cp_commit();

    const int NT = SEQ / 64;
    #pragma unroll 1
    for (int kt = 0; kt < NT; ++kt) {
        cp_wait<0>();
        __syncthreads();

        if (kt + 1 < NT) {
            const uint32_t boff = ((kt + 1) & 1) * F_STB;
            const size_t goff = (size_t)(kt + 1) * 64 * HDIM;
            cpasync16(kdst + boff,      kbase + goff);
            cpasync16(kdst + boff + 16, kbase + goff + 8);
            cpasync16(kdst + boff + 32, kbase + goff + 16);
            cpasync16(kdst + boff + 48, kbase + goff + 24);
            cpasync16(vdst + boff,      vbase + goff);
            cpasync16(vdst + boff + 16, vbase + goff + 8);
            cpasync16(vdst + boff + 32, vbase + goff + 16);
            cpasync16(vdst + boff + 48, vbase + goff + 24);
            cp_commit();
        }

        const uint32_t sb = (uint32_t)(kt & 1) * F_STB;

        // S = Q @ K^T  (fragment ping-pong on K B-frags)
        float s[2][8][4];
        #pragma unroll
        for (int mi = 0; mi < 2; ++mi)
            #pragma unroll
            for (int nf = 0; nf < 8; ++nf)
                #pragma unroll
                for (int j = 0; j < 4; ++j) s[mi][nf][j] = 0.0f;

        const uint32_t skw = skb + sb;
        {
            uint32_t bb[2][4];
            ldsm4(bb[0], skw);   // (kf=0, nfp=0)
            #pragma unroll
            for (int it = 0; it < 16; ++it) {
                const int kf  = it >> 2, nfp = it & 3;
                const int cur = it & 1,  nxt = cur ^ 1;
                if (it < 15) {
                    const int it2 = it + 1;
                    const int kf2 = it2 >> 2, nfp2 = it2 & 3;
                    ldsm4(bb[nxt], skw + (uint32_t)(nfp2 * 16 * 36) * 4 + kf2 * 32);
                }
                mma_f16(s[0][2 * nfp],     qf[0][kf], &bb[cur][0]);
                mma_f16(s[0][2 * nfp + 1], qf[0][kf], &bb[cur][2]);
                mma_f16(s[1][2 * nfp],     qf[1][kf], &bb[cur][0]);
                mma_f16(s[1][2 * nfp + 1], qf[1][kf], &bb[cur][2]);
            }
        }

        // Online softmax (log2 domain) + pack P into registers
        uint32_t pf[2][4][4];
        #pragma unroll
        for (int mi = 0; mi < 2; ++mi) {
            float mx0 = -1e30f, mx1 = -1e30f;
            #pragma unroll
            for (int nf = 0; nf < 8; ++nf) {
                mx0 = fmaxf(mx0, fmaxf(s[mi][nf][0], s[mi][nf][1]));
                mx1 = fmaxf(mx1, fmaxf(s[mi][nf][2], s[mi][nf][3]));
            }
            mx0 = fmaxf(mx0, __shfl_xor_sync(0xffffffffu, mx0, 1));
            mx0 = fmaxf(mx0, __shfl_xor_sync(0xffffffffu, mx0, 2));
            mx1 = fmaxf(mx1, __shfl_xor_sync(0xffffffffu, mx1, 1));
            mx1 = fmaxf(mx1, __shfl_xor_sync(0xffffffffu, mx1, 2));

            float mn0 = fmaxf(m_i[mi][0], mx0);
            float mn1 = fmaxf(m_i[mi][1], mx1);
            float corr0 = fexp2(m_i[mi][0] - mn0);
            float corr1 = fexp2(m_i[mi][1] - mn1);

            float rs0 = 0.0f, rs1 = 0.0f;
            #pragma unroll
            for (int nf = 0; nf < 8; ++nf) {
                s[mi][nf][0] = fexp2(s[mi][nf][0] - mn0);
                s[mi][nf][1] = fexp2(s[mi][nf][1] - mn0);
                s[mi][nf][2] = fexp2(s[mi][nf][2] - mn1);
                s[mi][nf][3] = fexp2(s[mi][nf][3] - mn1);
                rs0 += s[mi][nf][0] + s[mi][nf][1];
                rs1 += s[mi][nf][2] + s[mi][nf][3];
            }
            rs0 += __shfl_xor_sync(0xffffffffu, rs0, 1);
            rs0 += __shfl_xor_sync(0xffffffffu, rs0, 2);
            rs1 += __shfl_xor_sync(0xffffffffu, rs1, 1);
            rs1 += __shfl_xor_sync(0xffffffffu, rs1, 2);

            l_i[mi][0] = l_i[mi][0] * corr0 + rs0;
            l_i[mi][1] = l_i[mi][1] * corr1 + rs1;
            m_i[mi][0] = mn0;
            m_i[mi][1] = mn1;

            #pragma unroll
            for (int nf = 0; nf < 8; ++nf) {
                o[mi][nf][0] *= corr0; o[mi][nf][1] *= corr0;
                o[mi][nf][2] *= corr1; o[mi][nf][3] *= corr1;
            }

            #pragma unroll
            for (int kf = 0; kf < 4; ++kf) {
                pf[mi][kf][0] = packh(s[mi][2 * kf][0],     s[mi][2 * kf][1]);
                pf[mi][kf][1] = packh(s[mi][2 * kf][2],     s[mi][2 * kf][3]);
                pf[mi][kf][2] = packh(s[mi][2 * kf + 1][0], s[mi][2 * kf + 1][1]);
                pf[mi][kf][3] = packh(s[mi][2 * kf + 1][2], s[mi][2 * kf + 1][3]);
            }
        }

        // O += P @ V  (fragment ping-pong on V B-frags, ldmatrix.trans)
        const uint32_t svw = svb + sb;
        {
            uint32_t bb[2][4];
            ldsm4t(bb[0], svw);   // (kf=0, nfp=0)
            #pragma unroll
            for (int it = 0; it < 16; ++it) {
                const int kf  = it >> 2, nfp = it & 3;
                const int cur = it & 1,  nxt = cur ^ 1;
                if (it < 15) {
                    const int it2 = it + 1;
                    const int kf2 = it2 >> 2, nfp2 = it2 & 3;
                    ldsm4t(bb[nxt], svw + (uint32_t)(kf2 * 16 * 36) * 4 + nfp2 * 32);
                }
                mma_f16(o[0][2 * nfp],     pf[0][kf], &bb[cur][0]);
                mma_f16(o[0][2 * nfp + 1], pf[0][kf], &bb[cur][2]);
                mma_f16(o[1][2 * nfp],     pf[1][kf], &bb[cur][0]);
                mma_f16(o[1][2 * nfp + 1], pf[1][kf], &bb[cur][2]);
            }
        }
    }

    int bz = bh >> 3, h = bh & 7;
    #pragma unroll
    for (int mi = 0; mi < 2; ++mi) {
        float inv0 = 1.0f / l_i[mi][0];
        float inv1 = 1.0f / l_i[mi][1];
        int row0 = qt * 128 + w * 32 + mi * 16 + r;
        __half* op0 = O + ((size_t)bz * SEQ + row0) * EMBED + h * HDIM;
        __half* op1 = O + ((size_t)bz * SEQ + row0 + 8) * EMBED + h * HDIM;
        #pragma unroll
        for (int nf = 0; nf < 8; ++nf) {
            *(uint32_t*)(op0 + nf * 8 + 2 * cc) = packh(o[mi][nf][0] * inv0, o[mi][nf][1] * inv0);
            *(uint32_t*)(op1 + nf * 8 + 2 * cc) = packh(o[mi][nf][2] * inv1, o[mi][nf][3] * inv1);
        }
    }
}

extern "C" void kernel_launch(void* const* d_in, const int* in_sizes, int n_in,
                              void* d_out, int out_size) {
    const float* x  = (const float*)d_in[0];
    const float* Wq = (const float*)d_in[1];
    const float* bq = (const float*)d_in[2];
    const float* Wk = (const float*)d_in[3];
    const float* bk = (const float*)d_in[4];
    const float* Wv = (const float*)d_in[5];
    const float* bv = (const float*)d_in[6];
    const float* Wo = (const float*)d_in[7];
    const float* bo = (const float*)d_in[8];
    float* out = (float*)d_out;

    __half *gq, *gk, *gv, *go;
    cudaGetSymbolAddress((void**)&gq, g_q);
    cudaGetSymbolAddress((void**)&gk, g_k);
    cudaGetSymbolAddress((void**)&gv, g_v);
    cudaGetSymbolAddress((void**)&go, g_o);

    const int GEMM_SMEM  = 2 * 2 * 128 * 36 * 4;   // 73728
    const int FLASH_SMEM = 2 * 2 * 64 * 36 * 4;    // 36864
    cudaFuncSetAttribute(qkv_proj,  cudaFuncAttributeMaxDynamicSharedMemorySize, GEMM_SMEM);
    cudaFuncSetAttribute(out_proj,  cudaFuncAttributeMaxDynamicSharedMemorySize, GEMM_SMEM);
    cudaFuncSetAttribute(flash_mma, cudaFuncAttributeMaxDynamicSharedMemorySize, FLASH_SMEM);

    const int XC = MTOT * EMBED / 4;
    const int WC = EMBED * EMBED / 4;
    convert_f2h<<<(XC + 4 * WC) / 256, 256>>>(x, Wq, Wk, Wv, Wo);

    dim3 gridP(EMBED / 128, MTOT / 128, 3);   // (4, 64, 3)
    qkv_proj<<<gridP, 256, GEMM_SMEM>>>(bq, bk, bv);

    dim3 gridA(SEQ / 128, BATCH * NHEADS);    // (16, 32)
    flash_mma<<<gridA, 128, FLASH_SMEM>>>(gq, gk, gv, go);

    dim3 gridO(EMBED / 128, MTOT / 128);      // (4, 64)
    out_proj<<<gridO, 256, GEMM_SMEM>>>(bo, out);
}

// round 17
// speedup vs baseline: 1.0473x; 1.0100x over previous
#include <cuda_runtime.h>
#include <cuda_fp16.h>
#include <math.h>
#include <stdint.h>

#define EMBED  512
#define NHEADS 8
#define HDIM   64
#define BATCH  4
#define SEQ    2048
#define MTOT   (BATCH*SEQ)   // 8192

// Scratch (device globals — no runtime allocation)
__device__ __half g_xh[MTOT*EMBED];             // x in fp16
__device__ __half g_wh[4*EMBED*EMBED];          // Wq,Wk,Wv,Wo in fp16
__device__ __half g_q[BATCH*NHEADS*SEQ*HDIM];   // [B,H,S,D] fp16
__device__ __half g_k[BATCH*NHEADS*SEQ*HDIM];   // [B,H,S,D] fp16
__device__ __half g_v[BATCH*NHEADS*SEQ*HDIM];   // [B,H,S,D] fp16
__device__ __half g_o[BATCH*SEQ*EMBED];         // [B,S,E] fp16

__device__ __forceinline__ float gelu_f(float x) {
    return 0.5f * x * (1.0f + erff(x * 0.70710678118654752440f));
}

__device__ __forceinline__ uint32_t packh(float a, float b) {
    __half2 h = __floats2half2_rn(a, b);
    return *(uint32_t*)&h;
}

__device__ __forceinline__ float fexp2(float x) {
    float y;
    asm("ex2.approx.ftz.f32 %0, %1;" : "=f"(y) : "f"(x));
    return y;
}

__device__ __forceinline__ uint32_t sptr(const void* p) {
    return (uint32_t)__cvta_generic_to_shared(p);
}

__device__ __forceinline__ void cpasync16(uint32_t dst, const void* src) {
    asm volatile("cp.async.ca.shared.global [%0], [%1], 16;" :: "r"(dst), "l"(src));
}
__device__ __forceinline__ void cp_commit() {
    asm volatile("cp.async.commit_group;");
}
template<int N>
__device__ __forceinline__ void cp_wait() {
    asm volatile("cp.async.wait_group %0;" :: "n"(N));
}

__device__ __forceinline__ void mma_f16(float c[4], const uint32_t a[4], const uint32_t b[2]) {
    asm volatile(
        "mma.sync.aligned.m16n8k16.row.col.f32.f16.f16.f32 "
        "{%0,%1,%2,%3},{%4,%5,%6,%7},{%8,%9},{%0,%1,%2,%3};"
        : "+f"(c[0]), "+f"(c[1]), "+f"(c[2]), "+f"(c[3])
        : "r"(a[0]), "r"(a[1]), "r"(a[2]), "r"(a[3]), "r"(b[0]), "r"(b[1]));
}

__device__ __forceinline__ void ldsm4(uint32_t r[4], uint32_t saddr) {
    asm volatile("ldmatrix.sync.aligned.m8n8.x4.shared.b16 {%0,%1,%2,%3}, [%4];"
                 : "=r"(r[0]), "=r"(r[1]), "=r"(r[2]), "=r"(r[3]) : "r"(saddr));
}

__device__ __forceinline__ void ldsm4t(uint32_t r[4], uint32_t saddr) {
    asm volatile("ldmatrix.sync.aligned.m8n8.x4.trans.shared.b16 {%0,%1,%2,%3}, [%4];"
                 : "=r"(r[0]), "=r"(r[1]), "=r"(r[2]), "=r"(r[3]) : "r"(saddr));
}

// ---------------------------------------------------------------------------
// Convert x and all four weight matrices to fp16 (one memory-bound pass).
// ---------------------------------------------------------------------------
__global__ __launch_bounds__(256)
void convert_f2h(const float* __restrict__ x,
                 const float* __restrict__ Wq, const float* __restrict__ Wk,
                 const float* __restrict__ Wv, const float* __restrict__ Wo) {
    const int XC = MTOT * EMBED / 4;
    const int WC = EMBED * EMBED / 4;
    int i = blockIdx.x * 256 + threadIdx.x;
    float4 v;
    uint2* dst;
    if (i < XC) {
        v = ((const float4*)x)[i];
        dst = (uint2*)g_xh + i;
    } else {
        int j = i - XC;
        int w = j / WC, off = j - w * WC;
        const float* Ws = (w == 0) ? Wq : (w == 1) ? Wk : (w == 2) ? Wv : Wo;
        v = ((const float4*)Ws)[off];
        dst = (uint2*)g_wh + j;
    }
    uint2 p;
    p.x = packh(v.x, v.y);
    p.y = packh(v.z, v.w);
    *dst = p;
}

// ---------------------------------------------------------------------------
// GEMM core (R10/R14 config): C = gelu(A @ W^T + bias). Block tile 128x128,
// 8 warps (2m x 4n), warp tile 64x32, BK=64, 2-stage cp.async, 1 sync/iter.
// Dynamic smem: 2 stages x (A 18432B + W 18432B) = 73728B.
// ---------------------------------------------------------------------------
#define G_ABYTES 18432u
#define G_WOFF   G_ABYTES
#define G_STB    36864u

template<bool OHALF>
__device__ __forceinline__ void gemm_core(const __half* __restrict__ A,
                                          const __half* __restrict__ W,
                                          const float* __restrict__ bias, void* Cout) {
    extern __shared__ __align__(16) uint32_t dynsmem[];
    const uint32_t base = sptr(dynsmem);

    const int t    = threadIdx.x;
    const int lane = t & 31;
    const int warp = t >> 5;
    const int wm   = warp >> 2;       // 0..1
    const int wn   = warp & 3;        // 0..3
    const int m0   = blockIdx.y * 128;
    const int n0   = blockIdx.x * 128;
    const int r    = lane >> 2;
    const int cc   = lane & 3;

    const uint32_t a_loff = (((lane & 15) * 36) + ((lane >> 4) * 4)) * 4;
    const uint32_t b_loff = ((((lane & 7) + ((lane >> 4) * 8)) * 36) + (((lane >> 3) & 1) * 4)) * 4;
    const uint32_t as_w = base + (uint32_t)(wm * 64 * 36) * 4 + a_loff;
    const uint32_t ws_w = base + G_WOFF + (uint32_t)(wn * 32 * 36) * 4 + b_loff;

    const int lrow = t >> 1;
    const int lw16 = (t & 1) * 16;
    const __half* arow = A + (size_t)(m0 + lrow) * EMBED + lw16 * 2;
    const __half* wrow = W + (size_t)(n0 + lrow) * EMBED + lw16 * 2;
    const uint32_t adst = base + (uint32_t)(lrow * 36 + lw16) * 4;
    const uint32_t wdst = adst + G_WOFF;

    float acc[4][4][4];
    #pragma unroll
    for (int mi = 0; mi < 4; ++mi)
        #pragma unroll
        for (int ni = 0; ni < 4; ++ni)
            #pragma unroll
            for (int j = 0; j < 4; ++j) acc[mi][ni][j] = 0.0f;

    // prologue: issue chunk 0
    #pragma unroll
    for (int c = 0; c < 4; ++c) {
        cpasync16(adst + c * 16, arow + c * 8);
        cpasync16(wdst + c * 16, wrow + c * 8);
    }
    cp_commit();

    #pragma unroll 1
    for (int i = 0; i < 8; ++i) {
        cp_wait<0>();
        __syncthreads();

        if (i + 1 < 8) {
            const uint32_t so = (uint32_t)((i + 1) & 1) * G_STB;
            const int k0 = (i + 1) * 64;
            #pragma unroll
            for (int c = 0; c < 4; ++c) {
                cpasync16(adst + so + c * 16, arow + k0 + c * 8);
                cpasync16(wdst + so + c * 16, wrow + k0 + c * 8);
            }
            cp_commit();
        }

        const uint32_t sb = (uint32_t)(i & 1) * G_STB;
        const uint32_t aw = as_w + sb;
        const uint32_t ww = ws_w + sb;
        #pragma unroll
        for (int ks = 0; ks < 4; ++ks) {
            uint32_t a[4][4], b[2][4];
            #pragma unroll
            for (int mi = 0; mi < 4; ++mi)
                ldsm4(a[mi], aw + (uint32_t)(mi * 16 * 36) * 4 + ks * 32);
            #pragma unroll
            for (int np = 0; np < 2; ++np)
                ldsm4(b[np], ww + (uint32_t)(np * 16 * 36) * 4 + ks * 32);
            #pragma unroll
            for (int mi = 0; mi < 4; ++mi)
                #pragma unroll
                for (int np = 0; np < 2; ++np) {
                    mma_f16(acc[mi][2 * np],     a[mi], &b[np][0]);
                    mma_f16(acc[mi][2 * np + 1], a[mi], &b[np][2]);
                }
        }
    }

    // Epilogue: bias + gelu, store
    #pragma unroll
    for (int mi = 0; mi < 4; ++mi) {
        #pragma unroll
        for (int ni = 0; ni < 4; ++ni) {
            int row = m0 + wm * 64 + mi * 16 + r;
            int col = n0 + wn * 32 + ni * 8 + 2 * cc;
            float b0 = bias[col], b1 = bias[col + 1];
            float e00 = gelu_f(acc[mi][ni][0] + b0);
            float e01 = gelu_f(acc[mi][ni][1] + b1);
            float e10 = gelu_f(acc[mi][ni][2] + b0);
            float e11 = gelu_f(acc[mi][ni][3] + b1);
            if (!OHALF) {
                float* C = (float*)Cout;
                float2 v0 = {e00, e01}, v1 = {e10, e11};
                *(float2*)(C + (size_t)row * EMBED + col)       = v0;
                *(float2*)(C + (size_t)(row + 8) * EMBED + col) = v1;
            } else {
                __half* C = (__half*)Cout;
                int bz = row >> 11, s = row & (SEQ - 1);
                int h = col >> 6, d = col & 63;
                *(uint32_t*)&C[(((size_t)(bz * NHEADS + h) * SEQ + s) * HDIM + d)]       = packh(e00, e01);
                *(uint32_t*)&C[(((size_t)(bz * NHEADS + h) * SEQ + (s + 8)) * HDIM + d)] = packh(e10, e11);
            }
        }
    }
}

__global__ __launch_bounds__(256)
void qkv_proj(const float* __restrict__ bq, const float* __restrict__ bk,
              const float* __restrict__ bv) {
    const int z = blockIdx.z;
    const float* bias = (z == 0) ? bq : (z == 1) ? bk : bv;
    __half* C         = (z == 0) ? g_q : (z == 1) ? g_k : g_v;
    gemm_core<true>(g_xh, g_wh + (size_t)z * EMBED * EMBED, bias, C);
}

__global__ __launch_bounds__(256)
void out_proj(const float* __restrict__ bo, float* __restrict__ out) {
    gemm_core<false>(g_o, g_wh + (size_t)3 * EMBED * EMBED, bo, out);
}

// ---------------------------------------------------------------------------
// Flash attention with PV delayed one tile (softmax/PV overlap).
// Q,K,V: [B*H,S,64] fp16, O: [B,S,E] fp16. 128 threads = 4 warps; warp owns
// 32 q rows. KV tile = 64. 4-stage cp.async ring, 1 sync/tile.
// Per iter t: sync -> issue load(t+2) -> QK(t) mma -> PV(t-1) mma -> softmax(t).
// Dynamic smem: 4 stages x (K 9216B + V 9216B) = 73728B.
// ---------------------------------------------------------------------------
#define F_STB   18432u
#define F_VOFF  9216u

__global__ __launch_bounds__(128)
void flash_mma(const __half* __restrict__ Q, const __half* __restrict__ K,
               const __half* __restrict__ V, __half* __restrict__ O) {
    extern __shared__ __align__(16) uint32_t dynsmem[];
    const uint32_t base = sptr(dynsmem);

    const int t    = threadIdx.x;
    const int lane = t & 31;
    const int w    = t >> 5;
    const int bh   = blockIdx.y;
    const int qt   = blockIdx.x;
    const int r    = lane >> 2;
    const int cc   = lane & 3;

    const uint32_t b_loff = ((((lane & 7) + ((lane >> 4) * 8)) * 36) + (((lane >> 3) & 1) * 4)) * 4;
    const uint32_t t_loff = (((lane & 15) * 36) + ((lane >> 4) * 4)) * 4;
    const uint32_t skb = base + b_loff;
    const uint32_t svb = base + F_VOFF + t_loff;

    const int lrow = t >> 1;
    const int lw16 = (t & 1) * 16;
    const __half* kbase = K + ((size_t)bh * SEQ + lrow) * HDIM + lw16 * 2;
    const __half* vbase = V + ((size_t)bh * SEQ + lrow) * HDIM + lw16 * 2;
    const uint32_t kdst = base + (uint32_t)(lrow * 36 + lw16) * 4;
    const uint32_t vdst = kdst + F_VOFF;

    const float SC = 0.18033688011112042f;  // (1/8) * log2(e)
    const __half2 sc2 = __floats2half2_rn(SC, SC);
    uint32_t qf[2][4][4];
    const __half* qb = Q + ((size_t)bh * SEQ + qt * 128 + w * 32) * HDIM;
    #pragma unroll
    for (int mi = 0; mi < 2; ++mi) {
        #pragma unroll
        for (int kf = 0; kf < 4; ++kf) {
            int row0 = mi * 16 + r;
            uint32_t u0 = *(const uint32_t*)&qb[(size_t)row0 * HDIM + kf * 16 + cc * 2];
            uint32_t u1 = *(const uint32_t*)&qb[(size_t)(row0 + 8) * HDIM + kf * 16 + cc * 2];
            uint32_t u2 = *(const uint32_t*)&qb[(size_t)row0 * HDIM + kf * 16 + 8 + cc * 2];
            uint32_t u3 = *(const uint32_t*)&qb[(size_t)(row0 + 8) * HDIM + kf * 16 + 8 + cc * 2];
            __half2 h0 = __hmul2(*(__half2*)&u0, sc2);
            __half2 h1 = __hmul2(*(__half2*)&u1, sc2);
            __half2 h2 = __hmul2(*(__half2*)&u2, sc2);
            __half2 h3 = __hmul2(*(__half2*)&u3, sc2);
            qf[mi][kf][0] = *(uint32_t*)&h0;
            qf[mi][kf][1] = *(uint32_t*)&h1;
            qf[mi][kf][2] = *(uint32_t*)&h2;
            qf[mi][kf][3] = *(uint32_t*)&h3;
        }
    }

    float o[2][8][4];
    #pragma unroll
    for (int mi = 0; mi < 2; ++mi)
        #pragma unroll
        for (int nf = 0; nf < 8; ++nf)
            #pragma unroll
            for (int j = 0; j < 4; ++j) o[mi][nf][j] = 0.0f;
    float m_i[2][2] = {{-1e30f, -1e30f}, {-1e30f, -1e30f}};
    float l_i[2][2] = {{0.0f, 0.0f}, {0.0f, 0.0f}};
    uint32_t pf[2][4][4];   // P fragments of tile kt-1, consumed next iteration

    // prologue: issue tiles 0 and 1 (separate groups)
    #pragma unroll
    for (int tile = 0; tile < 2; ++tile) {
        const uint32_t boff = (uint32_t)tile * F_STB;
        const size_t goff = (size_t)tile * 64 * HDIM;
        cpasync16(kdst + boff,      kbase + goff);
        cpasync16(kdst + boff + 16, kbase + goff + 8);
        cpasync16(kdst + boff + 32, kbase + goff + 16);
        cpasync16(kdst + boff + 48, kbase + goff + 24);
        cpasync16(vdst + boff,      vbase + goff);
        cpasync16(vdst + boff + 16, vbase + goff + 8);
        cpasync16(vdst + boff + 32, vbase + goff + 16);
        cpasync16(vdst + boff + 48, vbase + goff + 24);
        cp_commit();
    }

    const int NT = SEQ / 64;
    #pragma unroll 1
    for (int kt = 0; kt < NT; ++kt) {
        if (kt < NT - 1) cp_wait<1>(); else cp_wait<0>();
        __syncthreads();   // tile kt ready; all warps finished iter kt-1 (incl PV(kt-2))

        // refill buf (kt+2)&3 = old tile kt-2 (last read by PV(kt-2) in iter kt-1)
        if (kt + 2 < NT) {
            const uint32_t boff = (uint32_t)((kt + 2) & 3) * F_STB;
            const size_t goff = (size_t)(kt + 2) * 64 * HDIM;
            cpasync16(kdst + boff,      kbase + goff);
            cpasync16(kdst + boff + 16, kbase + goff + 8);
            cpasync16(kdst + boff + 32, kbase + goff + 16);
            cpasync16(kdst + boff + 48, kbase + goff + 24);
            cpasync16(vdst + boff,      vbase + goff);
            cpasync16(vdst + boff + 16, vbase + goff + 8);
            cpasync16(vdst + boff + 32, vbase + goff + 16);
            cpasync16(vdst + boff + 48, vbase + goff + 24);
            cp_commit();
        }

        // ---- QK(kt): S = Q @ K^T ----
        float s[2][8][4];
        #pragma unroll
        for (int mi = 0; mi < 2; ++mi)
            #pragma unroll
            for (int nf = 0; nf < 8; ++nf)
                #pragma unroll
                for (int j = 0; j < 4; ++j) s[mi][nf][j] = 0.0f;

        const uint32_t skw = skb + (uint32_t)(kt & 3) * F_STB;
        #pragma unroll
        for (int kf = 0; kf < 4; ++kf) {
            #pragma unroll
            for (int nfp = 0; nfp < 4; ++nfp) {
                uint32_t bb[4];
                ldsm4(bb, skw + (uint32_t)(nfp * 16 * 36) * 4 + kf * 32);
                #pragma unroll
                for (int mi = 0; mi < 2; ++mi) {
                    mma_f16(s[mi][2 * nfp],     qf[mi][kf], &bb[0]);
                    mma_f16(s[mi][2 * nfp + 1], qf[mi][kf], &bb[2]);
                }
            }
        }

        // ---- PV(kt-1): O += P @ V (fills tensor pipe while QK drains) ----
        if (kt > 0) {
            const uint32_t svw = svb + (uint32_t)((kt - 1) & 3) * F_STB;
            #pragma unroll
            for (int kf = 0; kf < 4; ++kf) {
                #pragma unroll
                for (int nfp = 0; nfp < 4; ++nfp) {
                    uint32_t bb[4];
                    ldsm4t(bb, svw + (uint32_t)(kf * 16 * 36) * 4 + nfp * 32);
                    #pragma unroll
                    for (int mi = 0; mi < 2; ++mi) {
                        mma_f16(o[mi][2 * nfp],     pf[mi][kf], &bb[0]);
                        mma_f16(o[mi][2 * nfp + 1], pf[mi][kf], &bb[2]);
                    }
                }
            }
        }

        // ---- softmax(kt) (overlaps PV tail); o-rescale last ----
        #pragma unroll
        for (int mi = 0; mi < 2; ++mi) {
            float mx0 = -1e30f, mx1 = -1e30f;
            #pragma unroll
            for (int nf = 0; nf < 8; ++nf) {
                mx0 = fmaxf(mx0, fmaxf(s[mi][nf][0], s[mi][nf][1]));
                mx1 = fmaxf(mx1, fmaxf(s[mi][nf][2], s[mi][nf][3]));
            }
            mx0 = fmaxf(mx0, __shfl_xor_sync(0xffffffffu, mx0, 1));
            mx0 = fmaxf(mx0, __shfl_xor_sync(0xffffffffu, mx0, 2));
            mx1 = fmaxf(mx1, __shfl_xor_sync(0xffffffffu, mx1, 1));
            mx1 = fmaxf(mx1, __shfl_xor_sync(0xffffffffu, mx1, 2));

            float mn0 = fmaxf(m_i[mi][0], mx0);
            float mn1 = fmaxf(m_i[mi][1], mx1);
            float corr0 = fexp2(m_i[mi][0] - mn0);
            float corr1 = fexp2(m_i[mi][1] - mn1);

            float rs0 = 0.0f, rs1 = 0.0f;
            #pragma unroll
            for (int nf = 0; nf < 8; ++nf) {
                s[mi][nf][0] = fexp2(s[mi][nf][0] - mn0);
                s[mi][nf][1] = fexp2(s[mi][nf][1] - mn0);
                s[mi][nf][2] = fexp2(s[mi][nf][2] - mn1);
                s[mi][nf][3] = fexp2(s[mi][nf][3] - mn1);
                rs0 += s[mi][nf][0] + s[mi][nf][1];
                rs1 += s[mi][nf][2] + s[mi][nf][3];
            }
            rs0 += __shfl_xor_sync(0xffffffffu, rs0, 1);
            rs0 += __shfl_xor_sync(0xffffffffu, rs0, 2);
            rs1 += __shfl_xor_sync(0xffffffffu, rs1, 1);
            rs1 += __shfl_xor_sync(0xffffffffu, rs1, 2);

            l_i[mi][0] = l_i[mi][0] * corr0 + rs0;
            l_i[mi][1] = l_i[mi][1] * corr1 + rs1;
            m_i[mi][0] = mn0;
            m_i[mi][1] = mn1;

            // pack P for next iteration's PV
            #pragma unroll
            for (int kf = 0; kf < 4; ++kf) {
                pf[mi][kf][0] = packh(s[mi][2 * kf][0],     s[mi][2 * kf][1]);
                pf[mi][kf][1] = packh(s[mi][2 * kf][2],     s[mi][2 * kf][3]);
                pf[mi][kf][2] = packh(s[mi][2 * kf + 1][0], s[mi][2 * kf + 1][1]);
                pf[mi][kf][3] = packh(s[mi][2 * kf + 1][2], s[mi][2 * kf + 1][3]);
            }

            // rescale o last (waits on PV(kt-1) accumulators as late as possible)
            #pragma unroll
            for (int nf = 0; nf < 8; ++nf) {
                o[mi][nf][0] *= corr0; o[mi][nf][1] *= corr0;
                o[mi][nf][2] *= corr1; o[mi][nf][3] *= corr1;
            }
        }
    }

    // final PV(NT-1)
    {
        const uint32_t svw = svb + (uint32_t)((NT - 1) & 3) * F_STB;
        #pragma unroll
        for (int kf = 0; kf < 4; ++kf) {
            #pragma unroll
            for (int nfp = 0; nfp < 4; ++nfp) {
                uint32_t bb[4];
                ldsm4t(bb, svw + (uint32_t)(kf * 16 * 36) * 4 + nfp * 32);
                #pragma unroll
                for (int mi = 0; mi < 2; ++mi) {
                    mma_f16(o[mi][2 * nfp],     pf[mi][kf], &bb[0]);
                    mma_f16(o[mi][2 * nfp + 1], pf[mi][kf], &bb[2]);
                }
            }
        }
    }

    int bz = bh >> 3, h = bh & 7;
    #pragma unroll
    for (int mi = 0; mi < 2; ++mi) {
        float inv0 = 1.0f / l_i[mi][0];
        float inv1 = 1.0f / l_i[mi][1];
        int row0 = qt * 128 + w * 32 + mi * 16 + r;
        __half* op0 = O + ((size_t)bz * SEQ + row0) * EMBED + h * HDIM;
        __half* op1 = O + ((size_t)bz * SEQ + row0 + 8) * EMBED + h * HDIM;
        #pragma unroll
        for (int nf = 0; nf < 8; ++nf) {
            *(uint32_t*)(op0 + nf * 8 + 2 * cc) = packh(o[mi][nf][0] * inv0, o[mi][nf][1] * inv0);
            *(uint32_t*)(op1 + nf * 8 + 2 * cc) = packh(o[mi][nf][2] * inv1, o[mi][nf][3] * inv1);
        }
    }
}

extern "C" void kernel_launch(void* const* d_in, const int* in_sizes, int n_in,
                              void* d_out, int out_size) {
    const float* x  = (const float*)d_in[0];
    const float* Wq = (const float*)d_in[1];
    const float* bq = (const float*)d_in[2];
    const float* Wk = (const float*)d_in[3];
    const float* bk = (const float*)d_in[4];
    const float* Wv = (const float*)d_in[5];
    const float* bv = (const float*)d_in[6];
    const float* Wo = (const float*)d_in[7];
    const float* bo = (const float*)d_in[8];
    float* out = (float*)d_out;

    __half *gq, *gk, *gv, *go;
    cudaGetSymbolAddress((void**)&gq, g_q);
    cudaGetSymbolAddress((void**)&gk, g_k);
    cudaGetSymbolAddress((void**)&gv, g_v);
    cudaGetSymbolAddress((void**)&go, g_o);

    const int GEMM_SMEM  = 2 * 2 * 128 * 36 * 4;   // 73728
    const int FLASH_SMEM = 4 * 2 * 64 * 36 * 4;    // 73728 (4-stage ring)
    cudaFuncSetAttribute(qkv_proj,  cudaFuncAttributeMaxDynamicSharedMemorySize, GEMM_SMEM);
    cudaFuncSetAttribute(out_proj,  cudaFuncAttributeMaxDynamicSharedMemorySize, GEMM_SMEM);
    cudaFuncSetAttribute(flash_mma, cudaFuncAttributeMaxDynamicSharedMemorySize, FLASH_SMEM);

    const int XC = MTOT * EMBED / 4;
    const int WC = EMBED * EMBED / 4;
    convert_f2h<<<(XC + 4 * WC) / 256, 256>>>(x, Wq, Wk, Wv, Wo);

    dim3 gridP(EMBED / 128, MTOT / 128, 3);   // (4, 64, 3)
    qkv_proj<<<gridP, 256, GEMM_SMEM>>>(bq, bk, bv);

    dim3 gridA(SEQ / 128, BATCH * NHEADS);    // (16, 32)
    flash_mma<<<gridA, 128, FLASH_SMEM>>>(gq, gk, gv, go);

    dim3 gridO(EMBED / 128, MTOT / 128);      // (4, 64)
    out_proj<<<gridO, 256, GEMM_SMEM>>>(bo, out);
}